// round 8
// baseline (speedup 1.0000x reference)
#include <cuda_runtime.h>
#include <cstdint>

#define IMGS 32
#define H 768
#define W 768
#define NPIX (H*W)
#define TW 96            // output tile width
#define TH 64            // output tile height
#define WARPS 16
#define THREADS (WARPS*32)
#define ROWS_PW 6        // region rows per warp
#define EPS 1e-6f
#define RED_CTAS 64
#define RED_THREADS 256

__device__ float g_skel[2][IMGS * NPIX];
__device__ float g_acc[2][IMGS * NPIX];
__device__ float g_part[IMGS * RED_CTAS * 4];

__device__ __forceinline__ float4 f4min(float4 a, float4 b) {
    return make_float4(fminf(a.x, b.x), fminf(a.y, b.y), fminf(a.z, b.z), fminf(a.w, b.w));
}
__device__ __forceinline__ float4 f4max(float4 a, float4 b) {
    return make_float4(fmaxf(a.x, b.x), fmaxf(a.y, b.y), fmaxf(a.z, b.z), fmaxf(a.w, b.w));
}

// horizontal 3-window min/max across the 128-wide row (one warp = one row).
// lane-edge clamp (shfl returns own value) only corrupts the invalid ring.
__device__ __forceinline__ float4 hmin3(float4 b) {
    float lw = __shfl_up_sync(0xffffffffu, b.w, 1);
    float rx = __shfl_down_sync(0xffffffffu, b.x, 1);
    float4 r;
    r.x = fminf(fminf(lw, b.x), b.y);
    r.y = fminf(fminf(b.x, b.y), b.z);
    r.z = fminf(fminf(b.y, b.z), b.w);
    r.w = fminf(fminf(b.z, b.w), rx);
    return r;
}
__device__ __forceinline__ float4 hmax3(float4 b) {
    float lw = __shfl_up_sync(0xffffffffu, b.w, 1);
    float rx = __shfl_down_sync(0xffffffffu, b.x, 1);
    float4 r;
    r.x = fmaxf(fmaxf(lw, b.x), b.y);
    r.y = fmaxf(fmaxf(b.x, b.y), b.z);
    r.z = fmaxf(fmaxf(b.y, b.z), b.w);
    r.w = fmaxf(fmaxf(b.z, b.w), rx);
    return r;
}

__device__ __forceinline__ float4 selneg(bool m, float4 v) {
    const float NI_F = __int_as_float(0xff800000);
    return m ? make_float4(NI_F, NI_F, NI_F, NI_F) : v;
}

// boundary buffer element index: [par][warp][top/bot][lane]
__device__ __forceinline__ int BI(int par, int w, int tb, int lane) {
    return (par << 10) + (w << 6) + (tb << 5) + lane;
}

struct Ctx {
    int w, lane, r0;
    bool outw, xout;
    bool rm[8];   // row-outside-image mask for region rows r0-1 .. r0+6
};

// one iteration: erode in[] -> out[] (registers; pre-reduced boundaries via
// smem), then dilate+skel+acc post-sync. PAR = t&1 picks ping-pong buffers.
template <int PAR>
__device__ __forceinline__ void step_it(
    int t, bool dil, const Ctx& cx,
    float4 (&in)[ROWS_PW], float4 (&out)[ROWS_PW],
    float4 (&prod)[ROWS_PW], float4 (&acc)[ROWS_PW],
    float4& hkt, float4& hkb,
    float4* bmin, float4* bmax)
{
    const int w = cx.w, lane = cx.lane;
    const bool active = (cx.r0 + ROWS_PW - 1 >= t + 1) && (cx.r0 <= 94 - t);
    float4 hx0, hx5;

    if (active) {
        // ---- erosion: neighbor boundaries arrive pre-min'd; own rows 0/5
        //      reuse hkt/hkb kept from the previous iteration ----
        float4 hup = (w > 0)         ? bmin[BI(PAR, w - 1, 1, lane)] : hkt;
        float4 hdn = (w < WARPS - 1) ? bmin[BI(PAR, w + 1, 0, lane)] : hkb;
        float4 h1 = hmin3(in[1]);
        float4 h2 = hmin3(in[2]);
        float4 h3 = hmin3(in[3]);
        float4 h4 = hmin3(in[4]);
        out[0] = f4min(f4min(hup, hkt), h1);
        out[1] = f4min(f4min(hkt, h1), h2);
        out[2] = f4min(f4min(h1, h2), h3);
        out[3] = f4min(f4min(h2, h3), h4);
        out[4] = f4min(f4min(h3, h4), hkb);
        out[5] = f4min(f4min(h4, hkb), hdn);
        hkt = hmin3(out[0]);
        hkb = hmin3(out[ROWS_PW - 1]);
        bmin[BI(PAR ^ 1, w, 0, lane)] = hkt;
        bmin[BI(PAR ^ 1, w, 1, lane)] = hkb;
        if (dil) {
            // publish pre-maxed boundary rows (used by self AND neighbors)
            hx0 = hmax3(selneg(cx.xout, out[0]));
            hx5 = hmax3(selneg(cx.xout, out[ROWS_PW - 1]));
            bmax[BI(PAR ^ 1, w, 0, lane)] = hx0;
            bmax[BI(PAR ^ 1, w, 1, lane)] = hx5;
        }
        if (cx.outw) {
#pragma unroll
            for (int v = 0; v < ROWS_PW; ++v) {
                acc[v].x += out[v].x; acc[v].y += out[v].y;
                acc[v].z += out[v].z; acc[v].w += out[v].w;
            }
        }
    }
    __syncthreads();
    if (dil && cx.outw) {
        // dilation of E_{t+1}: interior pre-maxed locally, boundaries from smem
        float4 m1 = selneg(cx.rm[2], hmax3(selneg(cx.xout, out[1])));
        float4 m2 = selneg(cx.rm[3], hmax3(selneg(cx.xout, out[2])));
        float4 m3 = selneg(cx.rm[4], hmax3(selneg(cx.xout, out[3])));
        float4 m4 = selneg(cx.rm[5], hmax3(selneg(cx.xout, out[4])));
        float4 m0 = selneg(cx.rm[1], hx0);
        float4 m5 = selneg(cx.rm[6], hx5);
        float4 mU = selneg(cx.rm[0], bmax[BI(PAR ^ 1, w - 1, 1, lane)]);
        float4 mD = selneg(cx.rm[7], bmax[BI(PAR ^ 1, w + 1, 0, lane)]);
#define DROW(v, a, b, c) { \
        float4 d = f4max(f4max(a, b), c); \
        prod[v].x = fmaf(prod[v].x, d.x - in[v].x, prod[v].x); \
        prod[v].y = fmaf(prod[v].y, d.y - in[v].y, prod[v].y); \
        prod[v].z = fmaf(prod[v].z, d.z - in[v].z, prod[v].z); \
        prod[v].w = fmaf(prod[v].w, d.w - in[v].w, prod[v].w); }
        DROW(0, mU, m0, m1)
        DROW(1, m0, m1, m2)
        DROW(2, m1, m2, m3)
        DROW(3, m2, m3, m4)
        DROW(4, m3, m4, m5)
        DROW(5, m4, m5, mD)
#undef DROW
    }
}

// Fused morphology: each warp keeps a 6-row strip of the erosion state in
// registers; smem carries only pre-reduced boundary rows (ping-pong).
// grid = (8, 12, 64): z = img*2 + which (0 = pred, 1 = target)
__global__ __launch_bounds__(THREADS, 1)
void morph_kernel(const float* __restrict__ P, const float* __restrict__ Gt) {
    const int tz = blockIdx.z;
    const int img = tz >> 1;
    const int which = tz & 1;
    const float* __restrict__ src = (which ? Gt : P) + img * NPIX;

    const int tx0 = blockIdx.x * TW;
    const int ty0 = blockIdx.y * TH;
    const int tid = threadIdx.x;
    const int lane = tid & 31;
    const int w = tid >> 5;
    const int r0 = ROWS_PW * w;
    const int gx0 = tx0 - 16 + 4 * lane;

    extern __shared__ float4 sm4[];
    float4* bmin = sm4;          // [2][16][2][32] float4 = 32 KB
    float4* bmax = sm4 + 2048;   // [2][16][2][32] float4 = 32 KB

    const float PI_F = __int_as_float(0x7f800000);   // +inf

    float4 cur[ROWS_PW], nxt[ROWS_PW], prod[ROWS_PW], acc[ROWS_PW];

    // ---- load E_0 strip: rows ty0-16+r0+v, cols gx0..gx0+3; +inf outside ----
#pragma unroll
    for (int v = 0; v < ROWS_PW; ++v) {
        int gy = ty0 - 16 + r0 + v;
        float4 val = make_float4(PI_F, PI_F, PI_F, PI_F);
        if ((unsigned)gy < (unsigned)H && (unsigned)gx0 < (unsigned)W)
            val = *(const float4*)(src + gy * W + gx0);
        cur[v] = val;
        prod[v] = make_float4(1.f, 1.f, 1.f, 1.f);
        acc[v] = make_float4(0.f, 0.f, 0.f, 0.f);
    }
    float4 hkt = hmin3(cur[0]);
    float4 hkb = hmin3(cur[ROWS_PW - 1]);
    bmin[BI(0, w, 0, lane)] = hkt;
    bmin[BI(0, w, 1, lane)] = hkb;
    __syncthreads();

    Ctx cx;
    cx.w = w; cx.lane = lane; cx.r0 = r0;
    cx.outw = (w >= 2 && w <= 13);       // strips overlapping output rows 16..79
    cx.xout = (tx0 == 0 && lane < 4) || (tx0 + TW == W && lane >= 28);
    {
        const bool t0 = (ty0 == 0), b0 = (ty0 + TH == H);
#pragma unroll
        for (int k = 0; k < 8; ++k) {
            int r = r0 - 1 + k;
            cx.rm[k] = (t0 && r < 16) || (b0 && r > 79);
        }
    }

#pragma unroll 1
    for (int t = 0; t < 16; t += 2) {
        step_it<0>(t,     t     <= 10, cx, cur, nxt, prod, acc, hkt, hkb, bmin, bmax);
        step_it<1>(t + 1, t + 1 <= 10, cx, nxt, cur, prod, acc, hkt, hkb, bmin, bmax);
    }

    // ---- write outputs: region rows 16..79, cols = lanes 4..27 ----
    if (cx.outw && lane >= 4 && lane < 28) {
        float* skelp = g_skel[which] + img * NPIX;
        float* accp  = g_acc[which] + img * NPIX;
        const int gxo = tx0 + 4 * (lane - 4);
#pragma unroll
        for (int v = 0; v < ROWS_PW; ++v) {
            const int r = r0 + v;
            if (r >= 16 && r < 80) {
                const int off = (ty0 + r - 16) * W + gxo;
                float4 s = make_float4(1.f - prod[v].x, 1.f - prod[v].y,
                                       1.f - prod[v].z, 1.f - prod[v].w);
                *(float4*)(skelp + off) = s;
                *(float4*)(accp + off) = acc[v];
            }
        }
    }
}

// Per-image partial sums: a1 = sum(S_P*G*r_G), a2 = sum(S_P*r_G),
//                         b1 = sum(S_G*P*r_P), b2 = sum(S_G*r_P)
__global__ __launch_bounds__(RED_THREADS)
void reduce_kernel(const float* __restrict__ P, const float* __restrict__ G) {
    const int img = blockIdx.y;
    const int base = img * NPIX + blockIdx.x * (NPIX / RED_CTAS);
    const float inv16 = 1.0f / 16.0f;
    float a1 = 0.f, a2 = 0.f, b1 = 0.f, b2 = 0.f;
#pragma unroll
    for (int it = 0; it < 9; ++it) {
        int off = base + (it * RED_THREADS + threadIdx.x) * 4;
        float4 sp = *(const float4*)(&g_skel[0][off]);
        float4 sg = *(const float4*)(&g_skel[1][off]);
        float4 ap = *(const float4*)(&g_acc[0][off]);
        float4 ag = *(const float4*)(&g_acc[1][off]);
        float4 pv = *(const float4*)(&P[off]);
        float4 gv = *(const float4*)(&G[off]);
#define ACCUM(c) { \
        float rg = ag.c * inv16 * gv.c + EPS; \
        float rp = ap.c * inv16 * pv.c + EPS; \
        a1 += sp.c * gv.c * rg; a2 += sp.c * rg; \
        b1 += sg.c * pv.c * rp; b2 += sg.c * rp; }
        ACCUM(x) ACCUM(y) ACCUM(z) ACCUM(w)
#undef ACCUM
    }
#pragma unroll
    for (int o = 16; o; o >>= 1) {
        a1 += __shfl_down_sync(0xffffffffu, a1, o);
        a2 += __shfl_down_sync(0xffffffffu, a2, o);
        b1 += __shfl_down_sync(0xffffffffu, b1, o);
        b2 += __shfl_down_sync(0xffffffffu, b2, o);
    }
    __shared__ float sm[8][4];
    const int lane = threadIdx.x & 31, wrp = threadIdx.x >> 5;
    if (lane == 0) { sm[wrp][0] = a1; sm[wrp][1] = a2; sm[wrp][2] = b1; sm[wrp][3] = b2; }
    __syncthreads();
    if (threadIdx.x < 4) {
        float s = 0.f;
#pragma unroll
        for (int ww = 0; ww < 8; ++ww) s += sm[ww][threadIdx.x];
        g_part[(img * RED_CTAS + blockIdx.x) * 4 + threadIdx.x] = s;
    }
}

__global__ void final_kernel(float* __restrict__ out) {
    __shared__ float sums[IMGS][4];
    const int tid = threadIdx.x;
    if (tid < IMGS * 4) {
        int img = tid >> 2, k = tid & 3;
        float s = 0.f;
        for (int c = 0; c < RED_CTAS; ++c)
            s += g_part[(img * RED_CTAS + c) * 4 + k];
        sums[img][k] = s;
    }
    __syncthreads();
    if (tid == 0) {
        float loss = 0.f;
        for (int i = 0; i < IMGS; ++i) {
            float prec = sums[i][0] / (sums[i][1] + EPS);
            float rec  = sums[i][2] / (sums[i][3] + EPS);
            float cbd  = 2.f * prec * rec / (prec + rec + EPS);
            loss += 1.f - cbd;
        }
        out[0] = loss / (float)IMGS;
    }
}

extern "C" void kernel_launch(void* const* d_in, const int* in_sizes, int n_in,
                              void* d_out, int out_size) {
    const float* P = (const float*)d_in[0];   // pred
    const float* G = (const float*)d_in[1];   // target
    const size_t smem_bytes = 4096u * sizeof(float4);  // 65536
    cudaFuncSetAttribute(morph_kernel, cudaFuncAttributeMaxDynamicSharedMemorySize,
                         (int)smem_bytes);
    dim3 grid(W / TW, H / TH, IMGS * 2);
    morph_kernel<<<grid, THREADS, smem_bytes>>>(P, G);
    reduce_kernel<<<dim3(RED_CTAS, IMGS), RED_THREADS>>>(P, G);
    final_kernel<<<1, 128>>>((float*)d_out);
}

// round 9
// speedup vs baseline: 1.4311x; 1.4311x over previous
#include <cuda_runtime.h>
#include <cstdint>

#define IMGS 32
#define H 768
#define W 768
#define NPIX (H*W)
#define TW 96            // output tile width
#define TH 64            // output tile height
#define WARPS 16
#define THREADS (WARPS*32)
#define ROWS_PW 6        // region rows per warp
#define EPS 1e-6f
#define RED_CTAS 64
#define RED_THREADS 256

__device__ float g_skel[2][IMGS * NPIX];
__device__ float g_acc[2][IMGS * NPIX];
__device__ float g_part[IMGS * RED_CTAS * 4];

__device__ __forceinline__ float4 f4min(float4 a, float4 b) {
    return make_float4(fminf(a.x, b.x), fminf(a.y, b.y), fminf(a.z, b.z), fminf(a.w, b.w));
}
__device__ __forceinline__ float4 f4max(float4 a, float4 b) {
    return make_float4(fmaxf(a.x, b.x), fmaxf(a.y, b.y), fmaxf(a.z, b.z), fmaxf(a.w, b.w));
}

// horizontal 3-window min/max across the 128-wide row (one warp = one row).
// lane-edge clamp (shfl returns own value) only corrupts the invalid ring.
__device__ __forceinline__ float4 hmin3(float4 b) {
    float lw = __shfl_up_sync(0xffffffffu, b.w, 1);
    float rx = __shfl_down_sync(0xffffffffu, b.x, 1);
    float4 r;
    r.x = fminf(fminf(lw, b.x), b.y);
    r.y = fminf(fminf(b.x, b.y), b.z);
    r.z = fminf(fminf(b.y, b.z), b.w);
    r.w = fminf(fminf(b.z, b.w), rx);
    return r;
}
__device__ __forceinline__ float4 hmax3(float4 b) {
    float lw = __shfl_up_sync(0xffffffffu, b.w, 1);
    float rx = __shfl_down_sync(0xffffffffu, b.x, 1);
    float4 r;
    r.x = fmaxf(fmaxf(lw, b.x), b.y);
    r.y = fmaxf(fmaxf(b.x, b.y), b.z);
    r.z = fmaxf(fmaxf(b.y, b.z), b.w);
    r.w = fmaxf(fmaxf(b.z, b.w), rx);
    return r;
}

__device__ __forceinline__ float4 selneg(bool m, float4 v) {
    const float NI_F = __int_as_float(0xff800000);
    return m ? make_float4(NI_F, NI_F, NI_F, NI_F) : v;
}

// boundary buffer element index: [par][warp][top/bot][lane]
__device__ __forceinline__ int BI(int par, int w, int tb, int lane) {
    return (par << 10) + (w << 6) + (tb << 5) + lane;
}

struct Ctx {
    int w, lane, r0;
    bool outw, xout;
    bool rm[8];   // row-outside-image mask for region rows r0-1 .. r0+6
};

// one iteration: erode in[] -> out[] (registers; pre-reduced boundaries via
// smem, nothing carried across the sync in registers), then dilate+skel+acc.
// PAR = t&1 picks the bmin ping-pong; bmax also ping-pongs on PAR.
template <int PAR, bool EDGE>
__device__ __forceinline__ void step_it(
    int t, bool dil, const Ctx& cx,
    float4 (&in)[ROWS_PW], float4 (&out)[ROWS_PW],
    float4 (&prod)[ROWS_PW], float4 (&acc)[ROWS_PW],
    float4* bmin, float4* bmax)
{
    const int w = cx.w, lane = cx.lane;
    const bool active = (cx.r0 + ROWS_PW - 1 >= t + 1) && (cx.r0 <= 94 - t);

    if (active) {
        // ---- erosion: all boundary rows arrive pre-min'd from smem ----
        float4 hup = bmin[BI(PAR, (w > 0) ? w - 1 : w, (w > 0) ? 1 : 0, lane)];
        float4 hts = bmin[BI(PAR, w, 0, lane)];
        float4 hbs = bmin[BI(PAR, w, 1, lane)];
        float4 hdn = bmin[BI(PAR, (w < WARPS - 1) ? w + 1 : w,
                                  (w < WARPS - 1) ? 0 : 1, lane)];
        float4 h1 = hmin3(in[1]);
        float4 h2 = hmin3(in[2]);
        float4 h3 = hmin3(in[3]);
        float4 h4 = hmin3(in[4]);
        out[0] = f4min(f4min(hup, hts), h1);
        out[1] = f4min(f4min(hts, h1), h2);
        out[2] = f4min(f4min(h1, h2), h3);
        out[3] = f4min(f4min(h2, h3), h4);
        out[4] = f4min(f4min(h3, h4), hbs);
        out[5] = f4min(f4min(h4, hbs), hdn);
        bmin[BI(PAR ^ 1, w, 0, lane)] = hmin3(out[0]);
        bmin[BI(PAR ^ 1, w, 1, lane)] = hmin3(out[ROWS_PW - 1]);
        if (dil) {
            // publish pre-maxed boundary rows (self re-reads them post-sync)
            float4 a0 = EDGE ? selneg(cx.xout, out[0]) : out[0];
            float4 a5 = EDGE ? selneg(cx.xout, out[ROWS_PW - 1]) : out[ROWS_PW - 1];
            bmax[BI(PAR, w, 0, lane)] = hmax3(a0);
            bmax[BI(PAR, w, 1, lane)] = hmax3(a5);
        }
        if (cx.outw) {
#pragma unroll
            for (int v = 0; v < ROWS_PW; ++v) {
                acc[v].x += out[v].x; acc[v].y += out[v].y;
                acc[v].z += out[v].z; acc[v].w += out[v].w;
            }
        }
    }
    __syncthreads();
    if (dil && cx.outw) {
        // dilation of E_{t+1}: interior rows maxed locally, 4 boundary rows
        // (incl. own) read back pre-maxed from smem
        float4 mU = bmax[BI(PAR, w - 1, 1, lane)];
        float4 m0 = bmax[BI(PAR, w, 0, lane)];
        float4 m5 = bmax[BI(PAR, w, 1, lane)];
        float4 mD = bmax[BI(PAR, w + 1, 0, lane)];
        float4 m1, m2, m3, m4;
        if (EDGE) {
            m1 = selneg(cx.rm[2], hmax3(selneg(cx.xout, out[1])));
            m2 = selneg(cx.rm[3], hmax3(selneg(cx.xout, out[2])));
            m3 = selneg(cx.rm[4], hmax3(selneg(cx.xout, out[3])));
            m4 = selneg(cx.rm[5], hmax3(selneg(cx.xout, out[4])));
            mU = selneg(cx.rm[0], mU);
            m0 = selneg(cx.rm[1], m0);
            m5 = selneg(cx.rm[6], m5);
            mD = selneg(cx.rm[7], mD);
        } else {
            m1 = hmax3(out[1]);
            m2 = hmax3(out[2]);
            m3 = hmax3(out[3]);
            m4 = hmax3(out[4]);
        }
#define DROW(v, a, b, c) { \
        float4 d = f4max(f4max(a, b), c); \
        prod[v].x = fmaf(prod[v].x, d.x - in[v].x, prod[v].x); \
        prod[v].y = fmaf(prod[v].y, d.y - in[v].y, prod[v].y); \
        prod[v].z = fmaf(prod[v].z, d.z - in[v].z, prod[v].z); \
        prod[v].w = fmaf(prod[v].w, d.w - in[v].w, prod[v].w); }
        DROW(0, mU, m0, m1)
        DROW(1, m0, m1, m2)
        DROW(2, m1, m2, m3)
        DROW(3, m2, m3, m4)
        DROW(4, m3, m4, m5)
        DROW(5, m4, m5, mD)
#undef DROW
    }
}

template <bool EDGE>
__device__ __forceinline__ void morph_loop(
    const Ctx& cx, float4 (&cur)[ROWS_PW], float4 (&nxt)[ROWS_PW],
    float4 (&prod)[ROWS_PW], float4 (&acc)[ROWS_PW],
    float4* bmin, float4* bmax)
{
#pragma unroll 1
    for (int t = 0; t < 16; t += 2) {
        step_it<0, EDGE>(t,     t     <= 10, cx, cur, nxt, prod, acc, bmin, bmax);
        step_it<1, EDGE>(t + 1, t + 1 <= 10, cx, nxt, cur, prod, acc, bmin, bmax);
    }
}

// Fused morphology: each warp keeps a 6-row strip of the erosion state in
// registers; smem carries only pre-reduced boundary rows (ping-pong).
// grid = (8, 12, 64): z = img*2 + which (0 = pred, 1 = target)
__global__ __launch_bounds__(THREADS, 1)
void morph_kernel(const float* __restrict__ P, const float* __restrict__ Gt) {
    const int tz = blockIdx.z;
    const int img = tz >> 1;
    const int which = tz & 1;
    const float* __restrict__ src = (which ? Gt : P) + img * NPIX;

    const int tx0 = blockIdx.x * TW;
    const int ty0 = blockIdx.y * TH;
    const int tid = threadIdx.x;
    const int lane = tid & 31;
    const int w = tid >> 5;
    const int r0 = ROWS_PW * w;
    const int gx0 = tx0 - 16 + 4 * lane;

    extern __shared__ float4 sm4[];
    float4* bmin = sm4;          // [2][16][2][32] float4 = 32 KB
    float4* bmax = sm4 + 2048;   // [2][16][2][32] float4 = 32 KB

    const float PI_F = __int_as_float(0x7f800000);   // +inf

    float4 cur[ROWS_PW], nxt[ROWS_PW], prod[ROWS_PW], acc[ROWS_PW];

    // ---- load E_0 strip: rows ty0-16+r0+v, cols gx0..gx0+3; +inf outside ----
#pragma unroll
    for (int v = 0; v < ROWS_PW; ++v) {
        int gy = ty0 - 16 + r0 + v;
        float4 val = make_float4(PI_F, PI_F, PI_F, PI_F);
        if ((unsigned)gy < (unsigned)H && (unsigned)gx0 < (unsigned)W)
            val = *(const float4*)(src + gy * W + gx0);
        cur[v] = val;
        prod[v] = make_float4(1.f, 1.f, 1.f, 1.f);
        acc[v] = make_float4(0.f, 0.f, 0.f, 0.f);
    }
    bmin[BI(0, w, 0, lane)] = hmin3(cur[0]);
    bmin[BI(0, w, 1, lane)] = hmin3(cur[ROWS_PW - 1]);
    __syncthreads();

    Ctx cx;
    cx.w = w; cx.lane = lane; cx.r0 = r0;
    cx.outw = (w >= 2 && w <= 13);       // strips overlapping output rows 16..79
    const bool xb = (tx0 == 0) || (tx0 + TW == W);
    const bool t0 = (ty0 == 0), b0 = (ty0 + TH == H);
    cx.xout = (tx0 == 0 && lane < 4) || (tx0 + TW == W && lane >= 28);
#pragma unroll
    for (int k = 0; k < 8; ++k) {
        int r = r0 - 1 + k;
        cx.rm[k] = (t0 && r < 16) || (b0 && r > 79);
    }

    if (xb || t0 || b0)
        morph_loop<true>(cx, cur, nxt, prod, acc, bmin, bmax);
    else
        morph_loop<false>(cx, cur, nxt, prod, acc, bmin, bmax);

    // ---- write outputs: region rows 16..79, cols = lanes 4..27 ----
    if (cx.outw && lane >= 4 && lane < 28) {
        float* skelp = g_skel[which] + img * NPIX;
        float* accp  = g_acc[which] + img * NPIX;
        const int gxo = tx0 + 4 * (lane - 4);
#pragma unroll
        for (int v = 0; v < ROWS_PW; ++v) {
            const int r = r0 + v;
            if (r >= 16 && r < 80) {
                const int off = (ty0 + r - 16) * W + gxo;
                float4 s = make_float4(1.f - prod[v].x, 1.f - prod[v].y,
                                       1.f - prod[v].z, 1.f - prod[v].w);
                *(float4*)(skelp + off) = s;
                *(float4*)(accp + off) = acc[v];
            }
        }
    }
}

// Per-image partial sums: a1 = sum(S_P*G*r_G), a2 = sum(S_P*r_G),
//                         b1 = sum(S_G*P*r_P), b2 = sum(S_G*r_P)
__global__ __launch_bounds__(RED_THREADS)
void reduce_kernel(const float* __restrict__ P, const float* __restrict__ G) {
    const int img = blockIdx.y;
    const int base = img * NPIX + blockIdx.x * (NPIX / RED_CTAS);
    const float inv16 = 1.0f / 16.0f;
    float a1 = 0.f, a2 = 0.f, b1 = 0.f, b2 = 0.f;
#pragma unroll
    for (int it = 0; it < 9; ++it) {
        int off = base + (it * RED_THREADS + threadIdx.x) * 4;
        float4 sp = *(const float4*)(&g_skel[0][off]);
        float4 sg = *(const float4*)(&g_skel[1][off]);
        float4 ap = *(const float4*)(&g_acc[0][off]);
        float4 ag = *(const float4*)(&g_acc[1][off]);
        float4 pv = *(const float4*)(&P[off]);
        float4 gv = *(const float4*)(&G[off]);
#define ACCUM(c) { \
        float rg = ag.c * inv16 * gv.c + EPS; \
        float rp = ap.c * inv16 * pv.c + EPS; \
        a1 += sp.c * gv.c * rg; a2 += sp.c * rg; \
        b1 += sg.c * pv.c * rp; b2 += sg.c * rp; }
        ACCUM(x) ACCUM(y) ACCUM(z) ACCUM(w)
#undef ACCUM
    }
#pragma unroll
    for (int o = 16; o; o >>= 1) {
        a1 += __shfl_down_sync(0xffffffffu, a1, o);
        a2 += __shfl_down_sync(0xffffffffu, a2, o);
        b1 += __shfl_down_sync(0xffffffffu, b1, o);
        b2 += __shfl_down_sync(0xffffffffu, b2, o);
    }
    __shared__ float sm[8][4];
    const int lane = threadIdx.x & 31, wrp = threadIdx.x >> 5;
    if (lane == 0) { sm[wrp][0] = a1; sm[wrp][1] = a2; sm[wrp][2] = b1; sm[wrp][3] = b2; }
    __syncthreads();
    if (threadIdx.x < 4) {
        float s = 0.f;
#pragma unroll
        for (int ww = 0; ww < 8; ++ww) s += sm[ww][threadIdx.x];
        g_part[(img * RED_CTAS + blockIdx.x) * 4 + threadIdx.x] = s;
    }
}

__global__ void final_kernel(float* __restrict__ out) {
    __shared__ float sums[IMGS][4];
    const int tid = threadIdx.x;
    if (tid < IMGS * 4) {
        int img = tid >> 2, k = tid & 3;
        float s = 0.f;
        for (int c = 0; c < RED_CTAS; ++c)
            s += g_part[(img * RED_CTAS + c) * 4 + k];
        sums[img][k] = s;
    }
    __syncthreads();
    if (tid == 0) {
        float loss = 0.f;
        for (int i = 0; i < IMGS; ++i) {
            float prec = sums[i][0] / (sums[i][1] + EPS);
            float rec  = sums[i][2] / (sums[i][3] + EPS);
            float cbd  = 2.f * prec * rec / (prec + rec + EPS);
            loss += 1.f - cbd;
        }
        out[0] = loss / (float)IMGS;
    }
}

extern "C" void kernel_launch(void* const* d_in, const int* in_sizes, int n_in,
                              void* d_out, int out_size) {
    const float* P = (const float*)d_in[0];   // pred
    const float* G = (const float*)d_in[1];   // target
    const size_t smem_bytes = 4096u * sizeof(float4);  // 65536 (dynamic)
    cudaFuncSetAttribute(morph_kernel, cudaFuncAttributeMaxDynamicSharedMemorySize,
                         (int)smem_bytes);
    dim3 grid(W / TW, H / TH, IMGS * 2);
    morph_kernel<<<grid, THREADS, smem_bytes>>>(P, G);
    reduce_kernel<<<dim3(RED_CTAS, IMGS), RED_THREADS>>>(P, G);
    final_kernel<<<1, 128>>>((float*)d_out);
}